// round 2
// baseline (speedup 1.0000x reference)
#include <cuda_runtime.h>
#include <math.h>
#include <float.h>

// ---------------------------------------------------------------------------
// BottleneckBit: ternary-quantized bottleneck block, fp32 baseline (Round 1)
//   conv1: 1x1 1024->256, +bias, BN, SiLU
//   conv2: 3x3 256->256 pad1, +bias, BN, SiLU
//   conv3: 1x1 256->1024, +bias, BN, +residual, SiLU
// Weight quant: per-out-channel median(|w|) scale, ternary round/clip.
// BN scale folded into weights; conv bias + BN shift folded into bias.
// ---------------------------------------------------------------------------

#define BATCH 64
#define CIN   1024
#define WIDTH 256
#define COUT  1024
#define HIMG  14
#define WIMG  14
#define HW    196
#define NTOT  (BATCH*HW)      // 12544
#define IMGSTRIDE (CIN*HW)    // 200704

#define BM 128
#define BN 128
#define BK 16

// scratch (device globals: no allocation allowed)
__device__ float g_w1f[WIDTH*CIN];        // [o][c]
__device__ float g_w2f[9*WIDTH*WIDTH];    // [tap][o][c]
__device__ float g_w3f[COUT*WIDTH];       // [o][c]
__device__ float g_bias1[WIDTH];
__device__ float g_bias2[WIDTH];
__device__ float g_bias3[COUT];
__device__ float g_u1[WIDTH*NTOT];        // [c][n]  n = b*196+p
__device__ float g_u2[WIDTH*NTOT];        // [c][n]

__device__ __forceinline__ float silu_f(float x) {
    return x / (1.0f + expf(-x));
}

// ---------------------------------------------------------------------------
// Quantize one weight tensor (+fold BN) . One block per output channel.
// which: 1 -> w1 (K=1024), 2 -> w2 (K=2304, [tap][o][c] layout), 3 -> w3 (K=256)
// ---------------------------------------------------------------------------
__global__ void quant_kernel(const float* __restrict__ w,
                             const float* __restrict__ bconv,
                             const float* __restrict__ g,
                             const float* __restrict__ be,
                             const float* __restrict__ m,
                             const float* __restrict__ v,
                             int K, int NPad, int which)
{
    extern __shared__ float s[];
    const int o   = blockIdx.x;
    const int tid = threadIdx.x;
    const float* wrow = w + (size_t)o * K;

    for (int i = tid; i < NPad; i += blockDim.x)
        s[i] = (i < K) ? fabsf(wrow[i]) : FLT_MAX;
    __syncthreads();

    // bitonic sort ascending (pads = +inf end up at the top)
    for (int k = 2; k <= NPad; k <<= 1) {
        for (int j = k >> 1; j > 0; j >>= 1) {
            for (int i = tid; i < NPad; i += blockDim.x) {
                int ixj = i ^ j;
                if (ixj > i) {
                    float a = s[i], b = s[ixj];
                    bool up = ((i & k) == 0);
                    if ((a > b) == up) { s[i] = b; s[ixj] = a; }
                }
            }
            __syncthreads();
        }
    }

    __shared__ float sh_scale;
    if (tid == 0) {
        float med = 0.5f * (s[K/2 - 1] + s[K/2]);   // jnp.median, even K
        sh_scale = fmaxf(med, 1e-8f);
    }
    __syncthreads();
    const float sc = sh_scale;
    const float alpha = g[o] / sqrtf(v[o] + 1e-5f); // BN scale

    float* wf;
    float* biasf;
    if (which == 1)      { wf = g_w1f; biasf = g_bias1; }
    else if (which == 2) { wf = g_w2f; biasf = g_bias2; }
    else                 { wf = g_w3f; biasf = g_bias3; }

    for (int i = tid; i < K; i += blockDim.x) {
        float wv = wrow[i];
        float q  = rintf(wv / sc);               // round half-to-even, like jnp
        q = fminf(fmaxf(q, -1.0f), 1.0f);
        float val = (q * sc) * alpha;            // quantized weight, BN-folded
        if (which == 2) {
            int c = i / 9, tap = i - c * 9;      // OIHW: i = c*9 + kh*3 + kw
            wf[((size_t)tap * WIDTH + o) * WIDTH + c] = val;
        } else {
            wf[(size_t)o * K + i] = val;
        }
    }
    if (tid == 0)
        biasf[o] = bconv[o] * alpha + be[o] - m[o] * alpha;
}

// ---------------------------------------------------------------------------
// GEMM1: u1[o][n] = silu( sum_c w1f[o][c] * x[b][c][p] + bias1[o] )
//   M=256 (grid.y=2), N=12544 (grid.x=98), K=1024
// ---------------------------------------------------------------------------
__global__ __launch_bounds__(256, 2)
void gemm1_kernel(const float* __restrict__ x)
{
    __shared__ float As[BK][BM + 4];
    __shared__ float Bs[BK][BN];
    const int tid   = threadIdx.x;
    const int nBase = blockIdx.x * BN;
    const int mBase = blockIdx.y * BM;
    const int tx = tid & 15, ty = tid >> 4;

    const int col  = tid & 127;
    const int rowb = tid >> 7;          // 0 or 1
    const int n = nBase + col;
    const int b = n / HW;
    const int p = n - b * HW;
    const size_t xoff = (size_t)b * IMGSTRIDE + p;

    float acc[8][8];
#pragma unroll
    for (int i = 0; i < 8; i++)
#pragma unroll
        for (int j = 0; j < 8; j++) acc[i][j] = 0.0f;

    for (int kb = 0; kb < CIN; kb += BK) {
#pragma unroll
        for (int i = 0; i < 8; i++) {
            int idx = tid + i * 256;
            int k = idx & 15, mm = idx >> 4;
            As[k][mm] = g_w1f[(size_t)(mBase + mm) * CIN + kb + k];
        }
#pragma unroll
        for (int i = 0; i < 8; i++) {
            int r = rowb + 2 * i;
            Bs[r][col] = x[xoff + (size_t)(kb + r) * HW];
        }
        __syncthreads();
#pragma unroll
        for (int kk = 0; kk < BK; kk++) {
            float ra[8], rb[8];
#pragma unroll
            for (int i = 0; i < 8; i++) ra[i] = As[kk][ty * 8 + i];
#pragma unroll
            for (int j = 0; j < 8; j++) rb[j] = Bs[kk][tx * 8 + j];
#pragma unroll
            for (int i = 0; i < 8; i++)
#pragma unroll
                for (int j = 0; j < 8; j++)
                    acc[i][j] += ra[i] * rb[j];
        }
        __syncthreads();
    }

#pragma unroll
    for (int i = 0; i < 8; i++) {
        int o = mBase + ty * 8 + i;
        float bias = g_bias1[o];
#pragma unroll
        for (int j = 0; j < 8; j++) {
            int nn = nBase + tx * 8 + j;
            g_u1[(size_t)o * NTOT + nn] = silu_f(acc[i][j] + bias);
        }
    }
}

// ---------------------------------------------------------------------------
// CONV2 (implicit GEMM, 9 taps):
//   u2[o][n] = silu( sum_{tap,c} w2f[tap][o][c] * u1[c][shift(n,tap)] + bias2[o] )
//   M=256 (grid.y=2), N=12544 (grid.x=98), K = 9*256
// ---------------------------------------------------------------------------
__global__ __launch_bounds__(256, 2)
void conv2_kernel()
{
    __shared__ float As[BK][BM + 4];
    __shared__ float Bs[BK][BN];
    const int tid   = threadIdx.x;
    const int nBase = blockIdx.x * BN;
    const int mBase = blockIdx.y * BM;
    const int tx = tid & 15, ty = tid >> 4;

    const int col  = tid & 127;
    const int rowb = tid >> 7;
    const int n  = nBase + col;
    const int b  = n / HW;
    const int p  = n - b * HW;
    const int r0 = p / WIMG;
    const int c0 = p - r0 * WIMG;

    float acc[8][8];
#pragma unroll
    for (int i = 0; i < 8; i++)
#pragma unroll
        for (int j = 0; j < 8; j++) acc[i][j] = 0.0f;

    for (int tap = 0; tap < 9; tap++) {
        const int dh = tap / 3 - 1, dw = tap % 3 - 1;
        const int rr = r0 + dh, cc = c0 + dw;
        const bool valid = ((unsigned)rr < HIMG) && ((unsigned)cc < WIMG);
        const int nsrc = n + dh * WIMG + dw;   // stays inside image b when valid
        const float* wtap = g_w2f + (size_t)tap * WIDTH * WIDTH;

        for (int kb = 0; kb < WIDTH; kb += BK) {
#pragma unroll
            for (int i = 0; i < 8; i++) {
                int idx = tid + i * 256;
                int k = idx & 15, mm = idx >> 4;
                As[k][mm] = wtap[(size_t)(mBase + mm) * WIDTH + kb + k];
            }
#pragma unroll
            for (int i = 0; i < 8; i++) {
                int r = rowb + 2 * i;
                Bs[r][col] = valid ? g_u1[(size_t)(kb + r) * NTOT + nsrc] : 0.0f;
            }
            __syncthreads();
#pragma unroll
            for (int kk = 0; kk < BK; kk++) {
                float ra[8], rb[8];
#pragma unroll
                for (int i = 0; i < 8; i++) ra[i] = As[kk][ty * 8 + i];
#pragma unroll
                for (int j = 0; j < 8; j++) rb[j] = Bs[kk][tx * 8 + j];
#pragma unroll
                for (int i = 0; i < 8; i++)
#pragma unroll
                    for (int j = 0; j < 8; j++)
                        acc[i][j] += ra[i] * rb[j];
            }
            __syncthreads();
        }
    }

#pragma unroll
    for (int i = 0; i < 8; i++) {
        int o = mBase + ty * 8 + i;
        float bias = g_bias2[o];
#pragma unroll
        for (int j = 0; j < 8; j++) {
            int nn = nBase + tx * 8 + j;
            g_u2[(size_t)o * NTOT + nn] = silu_f(acc[i][j] + bias);
        }
    }
}

// ---------------------------------------------------------------------------
// GEMM3 + residual + SiLU, NCHW output:
//   out[b][o][p] = silu( sum_c w3f[o][c]*u2[c][n] + bias3[o] + x[b][o][p] )
//   M=1024 (grid.y=8), N=12544 (grid.x=98), K=256
// ---------------------------------------------------------------------------
__global__ __launch_bounds__(256, 2)
void gemm3_kernel(const float* __restrict__ x, float* __restrict__ out)
{
    __shared__ float As[BK][BM + 4];
    __shared__ float Bs[BK][BN];
    const int tid   = threadIdx.x;
    const int nBase = blockIdx.x * BN;
    const int mBase = blockIdx.y * BM;
    const int tx = tid & 15, ty = tid >> 4;

    const int col  = tid & 127;
    const int rowb = tid >> 7;
    const int n = nBase + col;

    float acc[8][8];
#pragma unroll
    for (int i = 0; i < 8; i++)
#pragma unroll
        for (int j = 0; j < 8; j++) acc[i][j] = 0.0f;

    for (int kb = 0; kb < WIDTH; kb += BK) {
#pragma unroll
        for (int i = 0; i < 8; i++) {
            int idx = tid + i * 256;
            int k = idx & 15, mm = idx >> 4;
            As[k][mm] = g_w3f[(size_t)(mBase + mm) * WIDTH + kb + k];
        }
#pragma unroll
        for (int i = 0; i < 8; i++) {
            int r = rowb + 2 * i;
            Bs[r][col] = g_u2[(size_t)(kb + r) * NTOT + n];
        }
        __syncthreads();
#pragma unroll
        for (int kk = 0; kk < BK; kk++) {
            float ra[8], rb[8];
#pragma unroll
            for (int i = 0; i < 8; i++) ra[i] = As[kk][ty * 8 + i];
#pragma unroll
            for (int j = 0; j < 8; j++) rb[j] = Bs[kk][tx * 8 + j];
#pragma unroll
            for (int i = 0; i < 8; i++)
#pragma unroll
                for (int j = 0; j < 8; j++)
                    acc[i][j] += ra[i] * rb[j];
        }
        __syncthreads();
    }

#pragma unroll
    for (int i = 0; i < 8; i++) {
        int o = mBase + ty * 8 + i;
        float bias = g_bias3[o];
#pragma unroll
        for (int j = 0; j < 8; j++) {
            int nn = nBase + tx * 8 + j;
            int b2 = nn / HW;
            int p2 = nn - b2 * HW;
            size_t oidx = ((size_t)b2 * COUT + o) * HW + p2;
            out[oidx] = silu_f(acc[i][j] + bias + x[oidx]);
        }
    }
}

// ---------------------------------------------------------------------------
extern "C" void kernel_launch(void* const* d_in, const int* in_sizes, int n_in,
                              void* d_out, int out_size)
{
    const float* x   = (const float*)d_in[0];
    const float* w1  = (const float*)d_in[1];
    const float* b1  = (const float*)d_in[2];
    const float* g1  = (const float*)d_in[3];
    const float* be1 = (const float*)d_in[4];
    const float* m1  = (const float*)d_in[5];
    const float* v1  = (const float*)d_in[6];
    const float* w2  = (const float*)d_in[7];
    const float* b2  = (const float*)d_in[8];
    const float* g2  = (const float*)d_in[9];
    const float* be2 = (const float*)d_in[10];
    const float* m2  = (const float*)d_in[11];
    const float* v2  = (const float*)d_in[12];
    const float* w3  = (const float*)d_in[13];
    const float* b3  = (const float*)d_in[14];
    const float* g3  = (const float*)d_in[15];
    const float* be3 = (const float*)d_in[16];
    const float* m3  = (const float*)d_in[17];
    const float* v3  = (const float*)d_in[18];
    float* out = (float*)d_out;

    // weight quantization + BN fold (every launch; deterministic)
    quant_kernel<<<WIDTH, 256, 1024 * sizeof(float)>>>(w1, b1, g1, be1, m1, v1,
                                                       1024, 1024, 1);
    quant_kernel<<<WIDTH, 256, 4096 * sizeof(float)>>>(w2, b2, g2, be2, m2, v2,
                                                       2304, 4096, 2);
    quant_kernel<<<COUT, 256, 256 * sizeof(float)>>>(w3, b3, g3, be3, m3, v3,
                                                     256, 256, 3);

    dim3 grid1(NTOT / BN, WIDTH / BM);   // (98, 2)
    gemm1_kernel<<<grid1, 256>>>(x);

    dim3 grid2(NTOT / BN, WIDTH / BM);   // (98, 2)
    conv2_kernel<<<grid2, 256>>>();

    dim3 grid3(NTOT / BN, COUT / BM);    // (98, 8)
    gemm3_kernel<<<grid3, 256>>>(x, out);
}

// round 4
// speedup vs baseline: 1.7035x; 1.7035x over previous
#include <cuda_runtime.h>
#include <cuda_bf16.h>
#include <math.h>
#include <float.h>
#include <stdint.h>

// ---------------------------------------------------------------------------
// BottleneckBit via ldmatrix + mma.sync bf16 (base sm_103 target — no 'a'
// features available to inline PTX in this build).
// Ternary weights exact in bf16 (scale folded into epilogue); activations
// split hi/lo bf16 (K doubled) => fp32-grade accuracy at tensor-core rate.
// Padded spatial layout: np = b*256 + (r+1)*16 + (c+1); pad rows stay zero
// (device globals zero-init, never written) so conv2 taps are constant shifts.
// ---------------------------------------------------------------------------

#define BATCH 64
#define CIN   1024
#define WIDTH 256
#define COUT  1024
#define HW    196
#define NPTOT 16384
#define U1_MARGIN 32
#define U1_ROWS (NPTOT + 2*U1_MARGIN)

#define PITCH 144          // bytes per smem row: 64 bf16 (128B) + 16B pad
#define TILEB (128*PITCH)  // 18432 bytes per 128x64 tile
#define BUFB  (2*TILEB)    // A + B
#define SMEMB (2*BUFB)     // double buffered = 73728

__device__ __nv_bfloat16 g_w1t[WIDTH*CIN];        // [o][c] ternary
__device__ __nv_bfloat16 g_w2t[9*WIDTH*WIDTH];    // [tap][o][c] ternary
__device__ __nv_bfloat16 g_w3t[COUT*WIDTH];       // [o][c] ternary
__device__ float g_scale1[WIDTH],  g_bias1[WIDTH];
__device__ float g_scale2[WIDTH],  g_bias2[WIDTH];
__device__ float g_scale3[COUT],   g_bias3[COUT];
__device__ __nv_bfloat16 g_xsplit[(size_t)NPTOT*2048];   // [np][k] hi|lo
__device__ __nv_bfloat16 g_u1[(size_t)U1_ROWS*512];      // [np+32][k] hi|lo
__device__ __nv_bfloat16 g_u2[(size_t)NPTOT*512];        // [np][k]   hi|lo

// ---------------------------------------------------------------------------
__device__ __forceinline__ uint32_t smem_u32(const void* p) {
    uint32_t a;
    asm("{ .reg .u64 t; cvta.to.shared.u64 t, %1; cvt.u32.u64 %0, t; }"
        : "=r"(a) : "l"(p));
    return a;
}
__device__ __forceinline__ void cpa16(uint32_t dst, const void* src) {
    asm volatile("cp.async.cg.shared.global [%0], [%1], 16;" :: "r"(dst), "l"(src));
}
#define CP_COMMIT() asm volatile("cp.async.commit_group;" ::: "memory")
#define CP_WAIT0()  asm volatile("cp.async.wait_group 0;" ::: "memory")
#define CP_WAIT1()  asm volatile("cp.async.wait_group 1;" ::: "memory")

__device__ __forceinline__ void ldmA(uint32_t* a, uint32_t addr) {
    asm volatile("ldmatrix.sync.aligned.m8n8.x4.shared.b16 {%0,%1,%2,%3}, [%4];"
                 : "=r"(a[0]), "=r"(a[1]), "=r"(a[2]), "=r"(a[3]) : "r"(addr));
}
__device__ __forceinline__ void ldmB(uint32_t* b, uint32_t addr) {
    asm volatile("ldmatrix.sync.aligned.m8n8.x2.shared.b16 {%0,%1}, [%2];"
                 : "=r"(b[0]), "=r"(b[1]) : "r"(addr));
}
__device__ __forceinline__ void mma16816(float* d, const uint32_t* a, const uint32_t* b) {
    asm volatile("mma.sync.aligned.m16n8k16.row.col.f32.bf16.bf16.f32 "
                 "{%0,%1,%2,%3}, {%4,%5,%6,%7}, {%8,%9}, {%0,%1,%2,%3};"
                 : "+f"(d[0]), "+f"(d[1]), "+f"(d[2]), "+f"(d[3])
                 : "r"(a[0]), "r"(a[1]), "r"(a[2]), "r"(a[3]), "r"(b[0]), "r"(b[1]));
}

__device__ __forceinline__ float silu_f(float x) { return x / (1.0f + expf(-x)); }

// compute one 128x128x64 chunk: warps 2(M) x 4(N), warp tile 64x32
__device__ __forceinline__ void mma_chunk(uint32_t Abuf, uint32_t Bbuf,
                                          int wm, int wn, int lane,
                                          float acc[4][4][4])
{
    const uint32_t aRowSel = (uint32_t)(lane & 15) * PITCH + (uint32_t)(lane >> 4) * 16;
    const uint32_t bRowSel = (uint32_t)(lane & 7)  * PITCH + (uint32_t)((lane >> 3) & 1) * 16;
#pragma unroll
    for (int ks = 0; ks < 4; ks++) {
        uint32_t afr[4][4];
#pragma unroll
        for (int mf = 0; mf < 4; mf++)
            ldmA(afr[mf], Abuf + (uint32_t)(wm * 64 + mf * 16) * PITCH + ks * 32 + aRowSel);
        uint32_t bfr[4][2];
#pragma unroll
        for (int nf = 0; nf < 4; nf++)
            ldmB(bfr[nf], Bbuf + (uint32_t)(wn * 32 + nf * 8) * PITCH + ks * 32 + bRowSel);
#pragma unroll
        for (int mf = 0; mf < 4; mf++)
#pragma unroll
            for (int nf = 0; nf < 4; nf++)
                mma16816(acc[mf][nf], afr[mf], bfr[nf]);
    }
}

// ---------------------------------------------------------------------------
// quant: one block per output channel; bitonic median of |w|; ternary bf16 out
// ---------------------------------------------------------------------------
__global__ void quant_kernel(const float* __restrict__ w,
                             const float* __restrict__ bconv,
                             const float* __restrict__ g,
                             const float* __restrict__ be,
                             const float* __restrict__ m,
                             const float* __restrict__ v,
                             int K, int NPad, int which)
{
    extern __shared__ float s[];
    const int o = blockIdx.x;
    const int tid = threadIdx.x;
    const float* wrow = w + (size_t)o * K;

    for (int i = tid; i < NPad; i += blockDim.x)
        s[i] = (i < K) ? fabsf(wrow[i]) : FLT_MAX;
    __syncthreads();

    for (int k = 2; k <= NPad; k <<= 1) {
        for (int j = k >> 1; j > 0; j >>= 1) {
            for (int i = tid; i < NPad; i += blockDim.x) {
                int ixj = i ^ j;
                if (ixj > i) {
                    float a = s[i], b = s[ixj];
                    bool up = ((i & k) == 0);
                    if ((a > b) == up) { s[i] = b; s[ixj] = a; }
                }
            }
            __syncthreads();
        }
    }

    __shared__ float sh_scale;
    if (tid == 0) {
        float med = 0.5f * (s[K/2 - 1] + s[K/2]);
        sh_scale = fmaxf(med, 1e-8f);
    }
    __syncthreads();
    const float sc = sh_scale;
    const float alpha = g[o] / sqrtf(v[o] + 1e-5f);

    for (int i = tid; i < K; i += blockDim.x) {
        float q = rintf(wrow[i] / sc);
        q = fminf(fmaxf(q, -1.0f), 1.0f);
        __nv_bfloat16 t = __float2bfloat16(q);   // exact: -1/0/1
        if (which == 1)      g_w1t[(size_t)o * CIN + i] = t;
        else if (which == 3) g_w3t[(size_t)o * WIDTH + i] = t;
        else {
            int c = i / 9, tap = i - c * 9;
            g_w2t[((size_t)tap * WIDTH + o) * WIDTH + c] = t;
        }
    }
    if (tid == 0) {
        float scal = sc * alpha;
        float bias = bconv[o] * alpha + be[o] - m[o] * alpha;
        if (which == 1)      { g_scale1[o] = scal; g_bias1[o] = bias; }
        else if (which == 2) { g_scale2[o] = scal; g_bias2[o] = bias; }
        else                 { g_scale3[o] = scal; g_bias3[o] = bias; }
    }
}

// ---------------------------------------------------------------------------
// x (NCHW fp32) -> g_xsplit [np][2048] bf16 hi/lo, via smem transpose
// ---------------------------------------------------------------------------
__global__ void __launch_bounds__(128) xsplit_kernel(const float* __restrict__ x)
{
    extern __shared__ float s[];
    const int b = blockIdx.x, cb = blockIdx.y;
    const float* xp = x + ((size_t)b * CIN + cb * 64) * HW;

    for (int idx = threadIdx.x; idx < 64 * HW; idx += 128) {
        int ci = idx / HW, p = idx - ci * HW;
        s[ci * 197 + p] = xp[(size_t)ci * HW + p];
    }
    __syncthreads();

    const int half = threadIdx.x >> 6;
    const int coff = threadIdx.x & 63;
    for (int p = 0; p < HW; p++) {
        int pr = p / 14, pc = p - pr * 14;
        int np = b * 256 + (pr + 1) * 16 + (pc + 1);
        float vv = s[coff * 197 + p];
        __nv_bfloat16 h = __float2bfloat16(vv);
        __nv_bfloat16 outv = (half == 0) ? h
                             : __float2bfloat16(vv - __bfloat162float(h));
        g_xsplit[(size_t)np * 2048 + (size_t)half * 1024 + cb * 64 + coff] = outv;
    }
}

// ---------------------------------------------------------------------------
// GEMM1: M=256 (grid.y=2), N=16384 (grid.x=128), K=2048. 32 chunks of 64.
// ---------------------------------------------------------------------------
__global__ void __launch_bounds__(256, 1) gemm1_mma()
{
    extern __shared__ char smem[];
    const uint32_t sb = smem_u32(smem);
    const int tid = threadIdx.x, lane = tid & 31, wid = tid >> 5;
    const int wm = wid & 1, wn = wid >> 1;
    const int nbase = blockIdx.x * 128;
    const int mbase = blockIdx.y * 128;
    const int NCH = 32;

    float acc[4][4][4];
#pragma unroll
    for (int a = 0; a < 4; a++)
#pragma unroll
        for (int b = 0; b < 4; b++)
#pragma unroll
            for (int c = 0; c < 4; c++) acc[a][b][c] = 0.0f;

    auto prefetch = [&](int i) {
        const uint32_t base = sb + (i & 1) * BUFB;
        const int kb = i * 64;
        const int kA = kb & 1023;
        for (int it = tid; it < 1024; it += 256) {
            int row = it >> 3, ch = it & 7;
            cpa16(base + row * PITCH + ch * 16,
                  &g_w1t[(size_t)(mbase + row) * CIN + kA + ch * 8]);
        }
        for (int it = tid; it < 1024; it += 256) {
            int row = it >> 3, ch = it & 7;
            cpa16(base + TILEB + row * PITCH + ch * 16,
                  &g_xsplit[(size_t)(nbase + row) * 2048 + kb + ch * 8]);
        }
        CP_COMMIT();
    };

    prefetch(0);
    for (int i = 0; i < NCH; i++) {
        if (i + 1 < NCH) { prefetch(i + 1); CP_WAIT1(); } else { CP_WAIT0(); }
        __syncthreads();
        const uint32_t base = sb + (i & 1) * BUFB;
        mma_chunk(base, base + TILEB, wm, wn, lane, acc);
        __syncthreads();
    }

#pragma unroll
    for (int mf = 0; mf < 4; mf++) {
#pragma unroll
        for (int half = 0; half < 2; half++) {
            const int o = mbase + wm * 64 + mf * 16 + (lane >> 2) + half * 8;
            const float sc = g_scale1[o], bi = g_bias1[o];
#pragma unroll
            for (int nf = 0; nf < 4; nf++) {
#pragma unroll
                for (int cc = 0; cc < 2; cc++) {
                    int np = nbase + wn * 32 + nf * 8 + (lane & 3) * 2 + cc;
                    int pr = (np >> 4) & 15, pc = np & 15;
                    if (pr >= 1 && pr <= 14 && pc >= 1 && pc <= 14) {
                        float y = sc * acc[mf][nf][half * 2 + cc] + bi;
                        float sv = silu_f(y);
                        __nv_bfloat16 h = __float2bfloat16(sv);
                        float lo = sv - __bfloat162float(h);
                        size_t row = (size_t)(np + U1_MARGIN) * 512;
                        g_u1[row + o] = h;
                        g_u1[row + 256 + o] = __float2bfloat16(lo);
                    }
                }
            }
        }
    }
}

// ---------------------------------------------------------------------------
// CONV2: 9 taps x K=512, 72 chunks. M=256 (grid.y=2), N=16384 (grid.x=128).
// ---------------------------------------------------------------------------
__global__ void __launch_bounds__(256, 1) conv2_mma()
{
    extern __shared__ char smem[];
    const uint32_t sb = smem_u32(smem);
    const int tid = threadIdx.x, lane = tid & 31, wid = tid >> 5;
    const int wm = wid & 1, wn = wid >> 1;
    const int nbase = blockIdx.x * 128;
    const int mbase = blockIdx.y * 128;
    const int NCH = 72;

    float acc[4][4][4];
#pragma unroll
    for (int a = 0; a < 4; a++)
#pragma unroll
        for (int b = 0; b < 4; b++)
#pragma unroll
            for (int c = 0; c < 4; c++) acc[a][b][c] = 0.0f;

    auto prefetch = [&](int i) {
        const uint32_t base = sb + (i & 1) * BUFB;
        const int tap = i >> 3, kc = i & 7;
        const int dh = tap / 3 - 1, dw = tap % 3 - 1;
        const int shift = dh * 16 + dw;
        const int kA = (kc * 64) & 255;           // hi/lo share weights
        const __nv_bfloat16* wtap = g_w2t + (size_t)tap * WIDTH * WIDTH;
        for (int it = tid; it < 1024; it += 256) {
            int row = it >> 3, ch = it & 7;
            cpa16(base + row * PITCH + ch * 16,
                  &wtap[(size_t)(mbase + row) * WIDTH + kA + ch * 8]);
        }
        for (int it = tid; it < 1024; it += 256) {
            int row = it >> 3, ch = it & 7;
            cpa16(base + TILEB + row * PITCH + ch * 16,
                  &g_u1[(size_t)(nbase + row + U1_MARGIN + shift) * 512 + kc * 64 + ch * 8]);
        }
        CP_COMMIT();
    };

    prefetch(0);
    for (int i = 0; i < NCH; i++) {
        if (i + 1 < NCH) { prefetch(i + 1); CP_WAIT1(); } else { CP_WAIT0(); }
        __syncthreads();
        const uint32_t base = sb + (i & 1) * BUFB;
        mma_chunk(base, base + TILEB, wm, wn, lane, acc);
        __syncthreads();
    }

#pragma unroll
    for (int mf = 0; mf < 4; mf++) {
#pragma unroll
        for (int half = 0; half < 2; half++) {
            const int o = mbase + wm * 64 + mf * 16 + (lane >> 2) + half * 8;
            const float sc = g_scale2[o], bi = g_bias2[o];
#pragma unroll
            for (int nf = 0; nf < 4; nf++) {
#pragma unroll
                for (int cc = 0; cc < 2; cc++) {
                    int np = nbase + wn * 32 + nf * 8 + (lane & 3) * 2 + cc;
                    int pr = (np >> 4) & 15, pc = np & 15;
                    if (pr >= 1 && pr <= 14 && pc >= 1 && pc <= 14) {
                        float y = sc * acc[mf][nf][half * 2 + cc] + bi;
                        float sv = silu_f(y);
                        __nv_bfloat16 h = __float2bfloat16(sv);
                        float lo = sv - __bfloat162float(h);
                        size_t row = (size_t)np * 512;
                        g_u2[row + o] = h;
                        g_u2[row + 256 + o] = __float2bfloat16(lo);
                    }
                }
            }
        }
    }
}

// ---------------------------------------------------------------------------
// GEMM3 + residual + SiLU -> NCHW fp32. M=1024 (grid.y=8), N (grid.x=128), K=512.
// ---------------------------------------------------------------------------
__global__ void __launch_bounds__(256, 1) gemm3_mma(const float* __restrict__ x,
                                                    float* __restrict__ out)
{
    extern __shared__ char smem[];
    const uint32_t sb = smem_u32(smem);
    const int tid = threadIdx.x, lane = tid & 31, wid = tid >> 5;
    const int wm = wid & 1, wn = wid >> 1;
    const int nbase = blockIdx.x * 128;
    const int mbase = blockIdx.y * 128;
    const int b_img = nbase >> 8;          // 128 cols stay within one image
    const int NCH = 8;

    float acc[4][4][4];
#pragma unroll
    for (int a = 0; a < 4; a++)
#pragma unroll
        for (int b = 0; b < 4; b++)
#pragma unroll
            for (int c = 0; c < 4; c++) acc[a][b][c] = 0.0f;

    auto prefetch = [&](int i) {
        const uint32_t base = sb + (i & 1) * BUFB;
        const int kb = i * 64;
        const int kA = kb & 255;
        for (int it = tid; it < 1024; it += 256) {
            int row = it >> 3, ch = it & 7;
            cpa16(base + row * PITCH + ch * 16,
                  &g_w3t[(size_t)(mbase + row) * WIDTH + kA + ch * 8]);
        }
        for (int it = tid; it < 1024; it += 256) {
            int row = it >> 3, ch = it & 7;
            cpa16(base + TILEB + row * PITCH + ch * 16,
                  &g_u2[(size_t)(nbase + row) * 512 + kb + ch * 8]);
        }
        CP_COMMIT();
    };

    prefetch(0);
    for (int i = 0; i < NCH; i++) {
        if (i + 1 < NCH) { prefetch(i + 1); CP_WAIT1(); } else { CP_WAIT0(); }
        __syncthreads();
        const uint32_t base = sb + (i & 1) * BUFB;
        mma_chunk(base, base + TILEB, wm, wn, lane, acc);
        __syncthreads();
    }

#pragma unroll
    for (int mf = 0; mf < 4; mf++) {
#pragma unroll
        for (int half = 0; half < 2; half++) {
            const int o = mbase + wm * 64 + mf * 16 + (lane >> 2) + half * 8;
            const float sc = g_scale3[o], bi = g_bias3[o];
#pragma unroll
            for (int nf = 0; nf < 4; nf++) {
#pragma unroll
                for (int cc = 0; cc < 2; cc++) {
                    int np = nbase + wn * 32 + nf * 8 + (lane & 3) * 2 + cc;
                    int pr = (np >> 4) & 15, pc = np & 15;
                    if (pr >= 1 && pr <= 14 && pc >= 1 && pc <= 14) {
                        int p = (pr - 1) * 14 + (pc - 1);
                        size_t idx = ((size_t)b_img * COUT + o) * HW + p;
                        float y = sc * acc[mf][nf][half * 2 + cc] + bi + x[idx];
                        out[idx] = silu_f(y);
                    }
                }
            }
        }
    }
}

// ---------------------------------------------------------------------------
extern "C" void kernel_launch(void* const* d_in, const int* in_sizes, int n_in,
                              void* d_out, int out_size)
{
    const float* x   = (const float*)d_in[0];
    const float* w1  = (const float*)d_in[1];
    const float* b1  = (const float*)d_in[2];
    const float* g1  = (const float*)d_in[3];
    const float* be1 = (const float*)d_in[4];
    const float* m1  = (const float*)d_in[5];
    const float* v1  = (const float*)d_in[6];
    const float* w2  = (const float*)d_in[7];
    const float* b2  = (const float*)d_in[8];
    const float* g2  = (const float*)d_in[9];
    const float* be2 = (const float*)d_in[10];
    const float* m2  = (const float*)d_in[11];
    const float* v2  = (const float*)d_in[12];
    const float* w3  = (const float*)d_in[13];
    const float* b3  = (const float*)d_in[14];
    const float* g3  = (const float*)d_in[15];
    const float* be3 = (const float*)d_in[16];
    const float* m3  = (const float*)d_in[17];
    const float* v3  = (const float*)d_in[18];
    float* out = (float*)d_out;

    cudaFuncSetAttribute(xsplit_kernel, cudaFuncAttributeMaxDynamicSharedMemorySize, 50432);
    cudaFuncSetAttribute(gemm1_mma, cudaFuncAttributeMaxDynamicSharedMemorySize, SMEMB);
    cudaFuncSetAttribute(conv2_mma, cudaFuncAttributeMaxDynamicSharedMemorySize, SMEMB);
    cudaFuncSetAttribute(gemm3_mma, cudaFuncAttributeMaxDynamicSharedMemorySize, SMEMB);

    quant_kernel<<<WIDTH, 256, 1024 * sizeof(float)>>>(w1, b1, g1, be1, m1, v1, 1024, 1024, 1);
    quant_kernel<<<WIDTH, 256, 4096 * sizeof(float)>>>(w2, b2, g2, be2, m2, v2, 2304, 4096, 2);
    quant_kernel<<<COUT,  256,  256 * sizeof(float)>>>(w3, b3, g3, be3, m3, v3,  256,  256, 3);

    xsplit_kernel<<<dim3(64, 16), 128, 50432>>>(x);

    gemm1_mma<<<dim3(128, 2), 256, SMEMB>>>();
    conv2_mma<<<dim3(128, 2), 256, SMEMB>>>();
    gemm3_mma<<<dim3(128, 8), 256, SMEMB>>>(x, out);
}

// round 5
// speedup vs baseline: 2.3597x; 1.3852x over previous
#include <cuda_runtime.h>
#include <cuda_bf16.h>
#include <math.h>
#include <float.h>
#include <stdint.h>

// ---------------------------------------------------------------------------
// BottleneckBit via ldmatrix + mma.sync bf16 (base sm_103 target).
// R5: interleaved hi/lo K-layout (paired 4B stores), compact N for gemm1/3,
// radix-select median (no bitonic sort), 2 CTAs/SM on the GEMMs.
// ---------------------------------------------------------------------------

#define BATCH 64
#define CIN   1024
#define WIDTH 256
#define COUT  1024
#define HW    196
#define NC    12544            // compact columns = 64*196
#define NPTOT 16384            // padded columns  = 64*256
#define U1_MARGIN 32
#define U1_ROWS (NPTOT + 2*U1_MARGIN)

#define PITCH 144              // smem row: 64 bf16 (128B) + 16B pad
#define TILEB (128*PITCH)
#define BUFB  (2*TILEB)
#define SMEMB (2*BUFB)         // 73728

// duplicated (hi/lo-interleaved) ternary weights
__device__ __nv_bfloat16 g_w1d[WIDTH*2048];        // [o][2k] == [o][2k+1]
__device__ __nv_bfloat16 g_w2d[9*WIDTH*512];       // [tap][o][512]
__device__ __nv_bfloat16 g_w3d[COUT*512];          // [o][512]
__device__ float g_scale1[WIDTH],  g_bias1[WIDTH];
__device__ float g_scale2[WIDTH],  g_bias2[WIDTH];
__device__ float g_scale3[COUT],   g_bias3[COUT];
__device__ __nv_bfloat16 g_xs[(size_t)NC*2048];    // [n][2c]=hi, [2c+1]=lo
__device__ __nv_bfloat16 g_u1[(size_t)U1_ROWS*512];// padded np rows, interleaved
__device__ __nv_bfloat16 g_u2[(size_t)NC*512];     // compact, interleaved

// ---------------------------------------------------------------------------
__device__ __forceinline__ uint32_t smem_u32(const void* p) {
    uint32_t a;
    asm("{ .reg .u64 t; cvta.to.shared.u64 t, %1; cvt.u32.u64 %0, t; }"
        : "=r"(a) : "l"(p));
    return a;
}
__device__ __forceinline__ void cpa16(uint32_t dst, const void* src) {
    asm volatile("cp.async.cg.shared.global [%0], [%1], 16;" :: "r"(dst), "l"(src));
}
#define CP_COMMIT() asm volatile("cp.async.commit_group;" ::: "memory")
#define CP_WAIT0()  asm volatile("cp.async.wait_group 0;" ::: "memory")
#define CP_WAIT1()  asm volatile("cp.async.wait_group 1;" ::: "memory")

__device__ __forceinline__ void ldmA(uint32_t* a, uint32_t addr) {
    asm volatile("ldmatrix.sync.aligned.m8n8.x4.shared.b16 {%0,%1,%2,%3}, [%4];"
                 : "=r"(a[0]), "=r"(a[1]), "=r"(a[2]), "=r"(a[3]) : "r"(addr));
}
__device__ __forceinline__ void ldmB(uint32_t* b, uint32_t addr) {
    asm volatile("ldmatrix.sync.aligned.m8n8.x2.shared.b16 {%0,%1}, [%2];"
                 : "=r"(b[0]), "=r"(b[1]) : "r"(addr));
}
__device__ __forceinline__ void mma16816(float* d, const uint32_t* a, const uint32_t* b) {
    asm volatile("mma.sync.aligned.m16n8k16.row.col.f32.bf16.bf16.f32 "
                 "{%0,%1,%2,%3}, {%4,%5,%6,%7}, {%8,%9}, {%0,%1,%2,%3};"
                 : "+f"(d[0]), "+f"(d[1]), "+f"(d[2]), "+f"(d[3])
                 : "r"(a[0]), "r"(a[1]), "r"(a[2]), "r"(a[3]), "r"(b[0]), "r"(b[1]));
}
__device__ __forceinline__ float silu_f(float x) { return x / (1.0f + expf(-x)); }

__device__ __forceinline__ void mma_chunk(uint32_t Abuf, uint32_t Bbuf,
                                          int wm, int wn, int lane,
                                          float acc[4][4][4])
{
    const uint32_t aRowSel = (uint32_t)(lane & 15) * PITCH + (uint32_t)(lane >> 4) * 16;
    const uint32_t bRowSel = (uint32_t)(lane & 7)  * PITCH + (uint32_t)((lane >> 3) & 1) * 16;
#pragma unroll
    for (int ks = 0; ks < 4; ks++) {
        uint32_t afr[4][4];
#pragma unroll
        for (int mf = 0; mf < 4; mf++)
            ldmA(afr[mf], Abuf + (uint32_t)(wm * 64 + mf * 16) * PITCH + ks * 32 + aRowSel);
        uint32_t bfr[4][2];
#pragma unroll
        for (int nf = 0; nf < 4; nf++)
            ldmB(bfr[nf], Bbuf + (uint32_t)(wn * 32 + nf * 8) * PITCH + ks * 32 + bRowSel);
#pragma unroll
        for (int mf = 0; mf < 4; mf++)
#pragma unroll
            for (int nf = 0; nf < 4; nf++)
                mma16816(acc[mf][nf], afr[mf], bfr[nf]);
    }
}

// ---------------------------------------------------------------------------
// quant: radix binary search for the two middle order stats of |w| (uint
// ordering == float ordering for non-negative). 256 threads, values in regs.
// ---------------------------------------------------------------------------
__device__ __forceinline__ uint32_t kth_uint(const uint32_t* v, int nv, int k,
                                             int* scnt, int tid)
{
    uint32_t lo = 0, hi = 0x7f7fffffu;
    while (lo < hi) {
        uint32_t mid = lo + ((hi - lo) >> 1);
        __syncthreads();
        if (tid == 0) *scnt = 0;
        __syncthreads();
        int c = 0;
        for (int i = 0; i < nv; i++) c += (v[i] <= mid) ? 1 : 0;
#pragma unroll
        for (int off = 16; off; off >>= 1) c += __shfl_down_sync(~0u, c, off);
        if ((tid & 31) == 0) atomicAdd(scnt, c);
        __syncthreads();
        if (*scnt >= k + 1) hi = mid; else lo = mid + 1;
    }
    return lo;
}

__global__ void quant_kernel(const float* __restrict__ w,
                             const float* __restrict__ bconv,
                             const float* __restrict__ g,
                             const float* __restrict__ be,
                             const float* __restrict__ m,
                             const float* __restrict__ v,
                             int K, int which)
{
    __shared__ int scnt;
    const int o = blockIdx.x;
    const int tid = threadIdx.x;
    const float* wrow = w + (size_t)o * K;

    uint32_t vals[9];
    const int nv = (K + 255) / 256;
    for (int j = 0; j < nv; j++) {
        int idx = tid + j * 256;
        vals[j] = (idx < K) ? __float_as_uint(fabsf(wrow[idx])) : 0xffffffffu;
    }

    uint32_t s0 = kth_uint(vals, nv, K / 2 - 1, &scnt, tid);
    uint32_t s1 = kth_uint(vals, nv, K / 2,     &scnt, tid);
    const float med = 0.5f * (__uint_as_float(s0) + __uint_as_float(s1));
    const float sc = fmaxf(med, 1e-8f);
    const float alpha = g[o] / sqrtf(v[o] + 1e-5f);

    for (int i = tid; i < K; i += 256) {
        float q = rintf(wrow[i] / sc);
        q = fminf(fmaxf(q, -1.0f), 1.0f);
        __nv_bfloat16 t = __float2bfloat16(q);   // exact ternary
        if (which == 1) {
            g_w1d[(size_t)o * 2048 + 2 * i] = t;
            g_w1d[(size_t)o * 2048 + 2 * i + 1] = t;
        } else if (which == 3) {
            g_w3d[(size_t)o * 512 + 2 * i] = t;
            g_w3d[(size_t)o * 512 + 2 * i + 1] = t;
        } else {
            int c = i / 9, tap = i - c * 9;
            size_t base = ((size_t)tap * WIDTH + o) * 512;
            g_w2d[base + 2 * c] = t;
            g_w2d[base + 2 * c + 1] = t;
        }
    }
    if (tid == 0) {
        float scal = sc * alpha;
        float bias = bconv[o] * alpha + be[o] - m[o] * alpha;
        if (which == 1)      { g_scale1[o] = scal; g_bias1[o] = bias; }
        else if (which == 2) { g_scale2[o] = scal; g_bias2[o] = bias; }
        else                 { g_scale3[o] = scal; g_bias3[o] = bias; }
    }
}

// ---------------------------------------------------------------------------
// xsplit: NCHW fp32 -> g_xs [n][2048] interleaved hi/lo, 4B paired stores.
// grid (64 b, 16 cb), 256 threads, smem 64*197 floats.
// ---------------------------------------------------------------------------
__global__ void __launch_bounds__(256) xsplit_kernel(const float* __restrict__ x)
{
    extern __shared__ float s[];
    const int b = blockIdx.x, cb = blockIdx.y;
    const float* xp = x + ((size_t)b * CIN + cb * 64) * HW;

    for (int idx = threadIdx.x; idx < 64 * HW; idx += 256) {
        int ci = idx / HW, p = idx - ci * HW;
        s[ci * 197 + p] = xp[(size_t)ci * HW + p];
    }
    __syncthreads();

    const int coff = threadIdx.x & 63;
    __nv_bfloat162* dst = (__nv_bfloat162*)g_xs;
    for (int p = threadIdx.x >> 6; p < HW; p += 4) {
        float vv = s[coff * 197 + p];
        __nv_bfloat16 h = __float2bfloat16(vv);
        __nv_bfloat16 l = __float2bfloat16(vv - __bfloat162float(h));
        int n = b * HW + p;
        dst[(size_t)n * 1024 + cb * 64 + coff] = __nv_bfloat162(h, l);
    }
}

// ---------------------------------------------------------------------------
// GEMM1: M=256 (grid.y=2), N=12544 compact (grid.x=98), K=2048, 32 chunks.
// ---------------------------------------------------------------------------
__global__ void __launch_bounds__(256, 2) gemm1_mma()
{
    extern __shared__ char smem[];
    const uint32_t sb = smem_u32(smem);
    const int tid = threadIdx.x, lane = tid & 31, wid = tid >> 5;
    const int wm = wid & 1, wn = wid >> 1;
    const int nbase = blockIdx.x * 128;
    const int mbase = blockIdx.y * 128;
    const int NCH = 32;

    float acc[4][4][4];
#pragma unroll
    for (int a = 0; a < 4; a++)
#pragma unroll
        for (int b = 0; b < 4; b++)
#pragma unroll
            for (int c = 0; c < 4; c++) acc[a][b][c] = 0.0f;

    auto prefetch = [&](int i) {
        const uint32_t base = sb + (i & 1) * BUFB;
        const int kb = i * 64;
        for (int it = tid; it < 1024; it += 256) {
            int row = it >> 3, ch = it & 7;
            cpa16(base + row * PITCH + ch * 16,
                  &g_w1d[(size_t)(mbase + row) * 2048 + kb + ch * 8]);
        }
        for (int it = tid; it < 1024; it += 256) {
            int row = it >> 3, ch = it & 7;
            cpa16(base + TILEB + row * PITCH + ch * 16,
                  &g_xs[(size_t)(nbase + row) * 2048 + kb + ch * 8]);
        }
        CP_COMMIT();
    };

    prefetch(0);
    for (int i = 0; i < NCH; i++) {
        if (i + 1 < NCH) { prefetch(i + 1); CP_WAIT1(); } else { CP_WAIT0(); }
        __syncthreads();
        const uint32_t base = sb + (i & 1) * BUFB;
        mma_chunk(base, base + TILEB, wm, wn, lane, acc);
        __syncthreads();
    }

    __nv_bfloat162* u1p = (__nv_bfloat162*)g_u1;
#pragma unroll
    for (int mf = 0; mf < 4; mf++) {
#pragma unroll
        for (int half = 0; half < 2; half++) {
            const int o = mbase + wm * 64 + mf * 16 + (lane >> 2) + half * 8;
            const float sc = g_scale1[o], bi = g_bias1[o];
#pragma unroll
            for (int nf = 0; nf < 4; nf++) {
#pragma unroll
                for (int cc = 0; cc < 2; cc++) {
                    int n = nbase + wn * 32 + nf * 8 + (lane & 3) * 2 + cc;
                    int b = n / HW, p = n - b * HW;
                    int pr = p / 14, pc = p - pr * 14;
                    int np = b * 256 + (pr + 1) * 16 + (pc + 1);
                    float sv = silu_f(sc * acc[mf][nf][half * 2 + cc] + bi);
                    __nv_bfloat16 h = __float2bfloat16(sv);
                    __nv_bfloat16 l = __float2bfloat16(sv - __bfloat162float(h));
                    u1p[(size_t)(np + U1_MARGIN) * 256 + o] = __nv_bfloat162(h, l);
                }
            }
        }
    }
}

// ---------------------------------------------------------------------------
// CONV2: padded N (grid.x=128), M=256 (grid.y=2), 9 taps x 8 k-chunks = 72.
// ---------------------------------------------------------------------------
__global__ void __launch_bounds__(256, 2) conv2_mma()
{
    extern __shared__ char smem[];
    const uint32_t sb = smem_u32(smem);
    const int tid = threadIdx.x, lane = tid & 31, wid = tid >> 5;
    const int wm = wid & 1, wn = wid >> 1;
    const int nbase = blockIdx.x * 128;
    const int mbase = blockIdx.y * 128;
    const int NCH = 72;

    float acc[4][4][4];
#pragma unroll
    for (int a = 0; a < 4; a++)
#pragma unroll
        for (int b = 0; b < 4; b++)
#pragma unroll
            for (int c = 0; c < 4; c++) acc[a][b][c] = 0.0f;

    auto prefetch = [&](int i) {
        const uint32_t base = sb + (i & 1) * BUFB;
        const int tap = i >> 3, kc = i & 7;
        const int dh = tap / 3 - 1, dw = tap % 3 - 1;
        const int shift = dh * 16 + dw;
        const __nv_bfloat16* wtap = g_w2d + (size_t)tap * WIDTH * 512;
        for (int it = tid; it < 1024; it += 256) {
            int row = it >> 3, ch = it & 7;
            cpa16(base + row * PITCH + ch * 16,
                  &wtap[(size_t)(mbase + row) * 512 + kc * 64 + ch * 8]);
        }
        for (int it = tid; it < 1024; it += 256) {
            int row = it >> 3, ch = it & 7;
            cpa16(base + TILEB + row * PITCH + ch * 16,
                  &g_u1[(size_t)(nbase + row + U1_MARGIN + shift) * 512 + kc * 64 + ch * 8]);
        }
        CP_COMMIT();
    };

    prefetch(0);
    for (int i = 0; i < NCH; i++) {
        if (i + 1 < NCH) { prefetch(i + 1); CP_WAIT1(); } else { CP_WAIT0(); }
        __syncthreads();
        const uint32_t base = sb + (i & 1) * BUFB;
        mma_chunk(base, base + TILEB, wm, wn, lane, acc);
        __syncthreads();
    }

    __nv_bfloat162* u2p = (__nv_bfloat162*)g_u2;
#pragma unroll
    for (int mf = 0; mf < 4; mf++) {
#pragma unroll
        for (int half = 0; half < 2; half++) {
            const int o = mbase + wm * 64 + mf * 16 + (lane >> 2) + half * 8;
            const float sc = g_scale2[o], bi = g_bias2[o];
#pragma unroll
            for (int nf = 0; nf < 4; nf++) {
#pragma unroll
                for (int cc = 0; cc < 2; cc++) {
                    int np = nbase + wn * 32 + nf * 8 + (lane & 3) * 2 + cc;
                    int pr = (np >> 4) & 15, pc = np & 15;
                    if (pr >= 1 && pr <= 14 && pc >= 1 && pc <= 14) {
                        int n = (np >> 8) * HW + (pr - 1) * 14 + (pc - 1);
                        float sv = silu_f(sc * acc[mf][nf][half * 2 + cc] + bi);
                        __nv_bfloat16 h = __float2bfloat16(sv);
                        __nv_bfloat16 l = __float2bfloat16(sv - __bfloat162float(h));
                        u2p[(size_t)n * 256 + o] = __nv_bfloat162(h, l);
                    }
                }
            }
        }
    }
}

// ---------------------------------------------------------------------------
// GEMM3 + residual + SiLU -> NCHW fp32. M=1024 (grid.y=8), N compact (98), K=512.
// ---------------------------------------------------------------------------
__global__ void __launch_bounds__(256, 2) gemm3_mma(const float* __restrict__ x,
                                                    float* __restrict__ out)
{
    extern __shared__ char smem[];
    const uint32_t sb = smem_u32(smem);
    const int tid = threadIdx.x, lane = tid & 31, wid = tid >> 5;
    const int wm = wid & 1, wn = wid >> 1;
    const int nbase = blockIdx.x * 128;
    const int mbase = blockIdx.y * 128;
    const int NCH = 8;

    float acc[4][4][4];
#pragma unroll
    for (int a = 0; a < 4; a++)
#pragma unroll
        for (int b = 0; b < 4; b++)
#pragma unroll
            for (int c = 0; c < 4; c++) acc[a][b][c] = 0.0f;

    auto prefetch = [&](int i) {
        const uint32_t base = sb + (i & 1) * BUFB;
        const int kb = i * 64;
        for (int it = tid; it < 1024; it += 256) {
            int row = it >> 3, ch = it & 7;
            cpa16(base + row * PITCH + ch * 16,
                  &g_w3d[(size_t)(mbase + row) * 512 + kb + ch * 8]);
        }
        for (int it = tid; it < 1024; it += 256) {
            int row = it >> 3, ch = it & 7;
            cpa16(base + TILEB + row * PITCH + ch * 16,
                  &g_u2[(size_t)(nbase + row) * 512 + kb + ch * 8]);
        }
        CP_COMMIT();
    };

    prefetch(0);
    for (int i = 0; i < NCH; i++) {
        if (i + 1 < NCH) { prefetch(i + 1); CP_WAIT1(); } else { CP_WAIT0(); }
        __syncthreads();
        const uint32_t base = sb + (i & 1) * BUFB;
        mma_chunk(base, base + TILEB, wm, wn, lane, acc);
        __syncthreads();
    }

#pragma unroll
    for (int mf = 0; mf < 4; mf++) {
#pragma unroll
        for (int half = 0; half < 2; half++) {
            const int o = mbase + wm * 64 + mf * 16 + (lane >> 2) + half * 8;
            const float sc = g_scale3[o], bi = g_bias3[o];
#pragma unroll
            for (int nf = 0; nf < 4; nf++) {
#pragma unroll
                for (int cc = 0; cc < 2; cc++) {
                    int n = nbase + wn * 32 + nf * 8 + (lane & 3) * 2 + cc;
                    int b = n / HW, p = n - b * HW;
                    size_t idx = ((size_t)b * COUT + o) * HW + p;
                    float y = sc * acc[mf][nf][half * 2 + cc] + bi + x[idx];
                    out[idx] = silu_f(y);
                }
            }
        }
    }
}

// ---------------------------------------------------------------------------
extern "C" void kernel_launch(void* const* d_in, const int* in_sizes, int n_in,
                              void* d_out, int out_size)
{
    const float* x   = (const float*)d_in[0];
    const float* w1  = (const float*)d_in[1];
    const float* b1  = (const float*)d_in[2];
    const float* g1  = (const float*)d_in[3];
    const float* be1 = (const float*)d_in[4];
    const float* m1  = (const float*)d_in[5];
    const float* v1  = (const float*)d_in[6];
    const float* w2  = (const float*)d_in[7];
    const float* b2  = (const float*)d_in[8];
    const float* g2  = (const float*)d_in[9];
    const float* be2 = (const float*)d_in[10];
    const float* m2  = (const float*)d_in[11];
    const float* v2  = (const float*)d_in[12];
    const float* w3  = (const float*)d_in[13];
    const float* b3  = (const float*)d_in[14];
    const float* g3  = (const float*)d_in[15];
    const float* be3 = (const float*)d_in[16];
    const float* m3  = (const float*)d_in[17];
    const float* v3  = (const float*)d_in[18];
    float* out = (float*)d_out;

    cudaFuncSetAttribute(xsplit_kernel, cudaFuncAttributeMaxDynamicSharedMemorySize, 50432);
    cudaFuncSetAttribute(gemm1_mma, cudaFuncAttributeMaxDynamicSharedMemorySize, SMEMB);
    cudaFuncSetAttribute(conv2_mma, cudaFuncAttributeMaxDynamicSharedMemorySize, SMEMB);
    cudaFuncSetAttribute(gemm3_mma, cudaFuncAttributeMaxDynamicSharedMemorySize, SMEMB);

    quant_kernel<<<WIDTH, 256>>>(w1, b1, g1, be1, m1, v1, 1024, 1);
    quant_kernel<<<WIDTH, 256>>>(w2, b2, g2, be2, m2, v2, 2304, 2);
    quant_kernel<<<COUT,  256>>>(w3, b3, g3, be3, m3, v3,  256, 3);

    xsplit_kernel<<<dim3(64, 16), 256, 50432>>>(x);

    gemm1_mma<<<dim3(98, 2), 256, SMEMB>>>();
    conv2_mma<<<dim3(128, 2), 256, SMEMB>>>();
    gemm3_mma<<<dim3(98, 8), 256, SMEMB>>>(x, out);
}

// round 6
// speedup vs baseline: 4.1108x; 1.7421x over previous
#include <cuda_runtime.h>
#include <cuda_fp16.h>
#include <math.h>
#include <float.h>
#include <stdint.h>

// ---------------------------------------------------------------------------
// BottleneckBit via ldmatrix + mma.sync fp16 (base sm_103 target).
// R6: single-fp16 activations (no hi/lo split -> half the GEMM FLOPs),
// compact N everywhere (conv2 boundary handled by zero-fill cp.async),
// fused quant launch with dual radix-select median.
// Ternary weights exact in fp16; scale/bias folded into fp32 epilogue.
// ---------------------------------------------------------------------------

#define BATCH 64
#define CIN   1024
#define WIDTH 256
#define COUT  1024
#define HW    196
#define NC    12544            // compact columns = 64*196 = 98*128

#define PITCH 144              // smem row: 64 fp16 (128B) + 16B pad
#define TILEB (128*PITCH)
#define BUFB  (2*TILEB)
#define SMEMB (2*BUFB)         // 73728

__device__ __half g_w1h[WIDTH*CIN];         // [o][c]
__device__ __half g_w2h[9*WIDTH*WIDTH];     // [tap][o][c]
__device__ __half g_w3h[COUT*WIDTH];        // [o][c]
__device__ float g_scale1[WIDTH],  g_bias1[WIDTH];
__device__ float g_scale2[WIDTH],  g_bias2[WIDTH];
__device__ float g_scale3[COUT],   g_bias3[COUT];
__device__ __half g_xs[(size_t)NC*CIN];     // [n][c]
__device__ __half g_u1[(size_t)NC*WIDTH];   // [n][c]
__device__ __half g_u2[(size_t)NC*WIDTH];   // [n][c]

// ---------------------------------------------------------------------------
__device__ __forceinline__ uint32_t smem_u32(const void* p) {
    uint32_t a;
    asm("{ .reg .u64 t; cvta.to.shared.u64 t, %1; cvt.u32.u64 %0, t; }"
        : "=r"(a) : "l"(p));
    return a;
}
__device__ __forceinline__ void cpa16(uint32_t dst, const void* src) {
    asm volatile("cp.async.cg.shared.global [%0], [%1], 16;" :: "r"(dst), "l"(src));
}
// zero-fill variant: copies sz bytes (0 or 16), zero-fills the rest of 16
__device__ __forceinline__ void cpa16z(uint32_t dst, const void* src, int sz) {
    asm volatile("cp.async.cg.shared.global [%0], [%1], 16, %2;"
                 :: "r"(dst), "l"(src), "r"(sz));
}
#define CP_COMMIT() asm volatile("cp.async.commit_group;" ::: "memory")
#define CP_WAIT0()  asm volatile("cp.async.wait_group 0;" ::: "memory")
#define CP_WAIT1()  asm volatile("cp.async.wait_group 1;" ::: "memory")

__device__ __forceinline__ void ldmA(uint32_t* a, uint32_t addr) {
    asm volatile("ldmatrix.sync.aligned.m8n8.x4.shared.b16 {%0,%1,%2,%3}, [%4];"
                 : "=r"(a[0]), "=r"(a[1]), "=r"(a[2]), "=r"(a[3]) : "r"(addr));
}
__device__ __forceinline__ void ldmB(uint32_t* b, uint32_t addr) {
    asm volatile("ldmatrix.sync.aligned.m8n8.x2.shared.b16 {%0,%1}, [%2];"
                 : "=r"(b[0]), "=r"(b[1]) : "r"(addr));
}
__device__ __forceinline__ void mma16816(float* d, const uint32_t* a, const uint32_t* b) {
    asm volatile("mma.sync.aligned.m16n8k16.row.col.f32.f16.f16.f32 "
                 "{%0,%1,%2,%3}, {%4,%5,%6,%7}, {%8,%9}, {%0,%1,%2,%3};"
                 : "+f"(d[0]), "+f"(d[1]), "+f"(d[2]), "+f"(d[3])
                 : "r"(a[0]), "r"(a[1]), "r"(a[2]), "r"(a[3]), "r"(b[0]), "r"(b[1]));
}
__device__ __forceinline__ float silu_f(float x) { return x / (1.0f + expf(-x)); }

__device__ __forceinline__ void mma_chunk(uint32_t Abuf, uint32_t Bbuf,
                                          int wm, int wn, int lane,
                                          float acc[4][4][4])
{
    const uint32_t aRowSel = (uint32_t)(lane & 15) * PITCH + (uint32_t)(lane >> 4) * 16;
    const uint32_t bRowSel = (uint32_t)(lane & 7)  * PITCH + (uint32_t)((lane >> 3) & 1) * 16;
#pragma unroll
    for (int ks = 0; ks < 4; ks++) {
        uint32_t afr[4][4];
#pragma unroll
        for (int mf = 0; mf < 4; mf++)
            ldmA(afr[mf], Abuf + (uint32_t)(wm * 64 + mf * 16) * PITCH + ks * 32 + aRowSel);
        uint32_t bfr[4][2];
#pragma unroll
        for (int nf = 0; nf < 4; nf++)
            ldmB(bfr[nf], Bbuf + (uint32_t)(wn * 32 + nf * 8) * PITCH + ks * 32 + bRowSel);
#pragma unroll
        for (int mf = 0; mf < 4; mf++)
#pragma unroll
            for (int nf = 0; nf < 4; nf++)
                mma16816(acc[mf][nf], afr[mf], bfr[nf]);
    }
}

// ---------------------------------------------------------------------------
// Fused quant for all three weights. 1536 blocks: [0,256)=w1, [256,512)=w2,
// [512,1536)=w3. Dual radix binary search finds both middle order stats of
// |w| (uint ordering == float ordering for non-negative) in one 31-pass loop.
// ---------------------------------------------------------------------------
__global__ void quant_all(const float* __restrict__ w1, const float* __restrict__ b1,
                          const float* __restrict__ g1, const float* __restrict__ be1,
                          const float* __restrict__ m1, const float* __restrict__ v1,
                          const float* __restrict__ w2, const float* __restrict__ b2,
                          const float* __restrict__ g2, const float* __restrict__ be2,
                          const float* __restrict__ m2, const float* __restrict__ v2,
                          const float* __restrict__ w3, const float* __restrict__ b3,
                          const float* __restrict__ g3, const float* __restrict__ be3,
                          const float* __restrict__ m3, const float* __restrict__ v3)
{
    __shared__ int scnt0, scnt1;
    const int blk = blockIdx.x;
    const int tid = threadIdx.x;

    int which, o, K;
    const float *w, *bc, *g, *be, *m, *v;
    if (blk < 256)      { which = 1; o = blk;       K = 1024; w = w1; bc = b1; g = g1; be = be1; m = m1; v = v1; }
    else if (blk < 512) { which = 2; o = blk - 256; K = 2304; w = w2; bc = b2; g = g2; be = be2; m = m2; v = v2; }
    else                { which = 3; o = blk - 512; K = 256;  w = w3; bc = b3; g = g3; be = be3; m = m3; v = v3; }

    const float* wrow = w + (size_t)o * K;
    uint32_t vals[9];
    const int nv = (K + 255) / 256;
    for (int j = 0; j < nv; j++) {
        int idx = tid + j * 256;
        vals[j] = (idx < K) ? __float_as_uint(fabsf(wrow[idx])) : 0xffffffffu;
    }

    const int k0 = K / 2 - 1, k1 = K / 2;
    uint32_t lo0 = 0, hi0 = 0x7f7fffffu, lo1 = 0, hi1 = 0x7f7fffffu;
    while (lo0 < hi0 || lo1 < hi1) {
        uint32_t mid0 = lo0 + ((hi0 - lo0) >> 1);
        uint32_t mid1 = lo1 + ((hi1 - lo1) >> 1);
        __syncthreads();
        if (tid == 0) { scnt0 = 0; scnt1 = 0; }
        __syncthreads();
        int c0 = 0, c1 = 0;
        for (int j = 0; j < nv; j++) {
            c0 += (vals[j] <= mid0) ? 1 : 0;
            c1 += (vals[j] <= mid1) ? 1 : 0;
        }
#pragma unroll
        for (int off = 16; off; off >>= 1) {
            c0 += __shfl_down_sync(~0u, c0, off);
            c1 += __shfl_down_sync(~0u, c1, off);
        }
        if ((tid & 31) == 0) { atomicAdd(&scnt0, c0); atomicAdd(&scnt1, c1); }
        __syncthreads();
        if (lo0 < hi0) { if (scnt0 >= k0 + 1) hi0 = mid0; else lo0 = mid0 + 1; }
        if (lo1 < hi1) { if (scnt1 >= k1 + 1) hi1 = mid1; else lo1 = mid1 + 1; }
    }
    const float med = 0.5f * (__uint_as_float(lo0) + __uint_as_float(lo1));
    const float sc = fmaxf(med, 1e-8f);
    const float alpha = g[o] / sqrtf(v[o] + 1e-5f);

    for (int i = tid; i < K; i += 256) {
        float q = rintf(wrow[i] / sc);
        q = fminf(fmaxf(q, -1.0f), 1.0f);
        __half t = __float2half_rn(q);          // exact ternary
        if (which == 1)      g_w1h[(size_t)o * CIN + i] = t;
        else if (which == 3) g_w3h[(size_t)o * WIDTH + i] = t;
        else {
            int c = i / 9, tap = i - c * 9;
            g_w2h[((size_t)tap * WIDTH + o) * WIDTH + c] = t;
        }
    }
    if (tid == 0) {
        float scal = sc * alpha;
        float bias = bc[o] * alpha + be[o] - m[o] * alpha;
        if (which == 1)      { g_scale1[o] = scal; g_bias1[o] = bias; }
        else if (which == 2) { g_scale2[o] = scal; g_bias2[o] = bias; }
        else                 { g_scale3[o] = scal; g_bias3[o] = bias; }
    }
}

// ---------------------------------------------------------------------------
// xconv: NCHW fp32 -> g_xs [n][1024] fp16 via smem transpose.
// grid (64 b, 16 cb), 256 threads.
// ---------------------------------------------------------------------------
__global__ void __launch_bounds__(256) xconv_kernel(const float* __restrict__ x)
{
    extern __shared__ float s[];
    const int b = blockIdx.x, cb = blockIdx.y;
    const float* xp = x + ((size_t)b * CIN + cb * 64) * HW;

    for (int idx = threadIdx.x; idx < 64 * HW; idx += 256) {
        int ci = idx / HW, p = idx - ci * HW;
        s[ci * 197 + p] = xp[(size_t)ci * HW + p];
    }
    __syncthreads();

    const int coff = threadIdx.x & 63;
    for (int p = threadIdx.x >> 6; p < HW; p += 4) {
        int n = b * HW + p;
        g_xs[(size_t)n * CIN + cb * 64 + coff] = __float2half_rn(s[coff * 197 + p]);
    }
}

// ---------------------------------------------------------------------------
// GEMM1: M=256 (grid.y=2), N=12544 (grid.x=98), K=1024, 16 chunks.
// ---------------------------------------------------------------------------
__global__ void __launch_bounds__(256, 2) gemm1_mma()
{
    extern __shared__ char smem[];
    const uint32_t sb = smem_u32(smem);
    const int tid = threadIdx.x, lane = tid & 31, wid = tid >> 5;
    const int wm = wid & 1, wn = wid >> 1;
    const int nbase = blockIdx.x * 128;
    const int mbase = blockIdx.y * 128;
    const int NCH = 16;

    float acc[4][4][4];
#pragma unroll
    for (int a = 0; a < 4; a++)
#pragma unroll
        for (int b = 0; b < 4; b++)
#pragma unroll
            for (int c = 0; c < 4; c++) acc[a][b][c] = 0.0f;

    auto prefetch = [&](int i) {
        const uint32_t base = sb + (i & 1) * BUFB;
        const int kb = i * 64;
        for (int it = tid; it < 1024; it += 256) {
            int row = it >> 3, ch = it & 7;
            cpa16(base + row * PITCH + ch * 16,
                  &g_w1h[(size_t)(mbase + row) * CIN + kb + ch * 8]);
        }
        for (int it = tid; it < 1024; it += 256) {
            int row = it >> 3, ch = it & 7;
            cpa16(base + TILEB + row * PITCH + ch * 16,
                  &g_xs[(size_t)(nbase + row) * CIN + kb + ch * 8]);
        }
        CP_COMMIT();
    };

    prefetch(0);
    for (int i = 0; i < NCH; i++) {
        if (i + 1 < NCH) { prefetch(i + 1); CP_WAIT1(); } else { CP_WAIT0(); }
        __syncthreads();
        const uint32_t base = sb + (i & 1) * BUFB;
        mma_chunk(base, base + TILEB, wm, wn, lane, acc);
        __syncthreads();
    }

#pragma unroll
    for (int mf = 0; mf < 4; mf++) {
#pragma unroll
        for (int half = 0; half < 2; half++) {
            const int o = mbase + wm * 64 + mf * 16 + (lane >> 2) + half * 8;
            const float sc = g_scale1[o], bi = g_bias1[o];
#pragma unroll
            for (int nf = 0; nf < 4; nf++) {
#pragma unroll
                for (int cc = 0; cc < 2; cc++) {
                    int n = nbase + wn * 32 + nf * 8 + (lane & 3) * 2 + cc;
                    float sv = silu_f(sc * acc[mf][nf][half * 2 + cc] + bi);
                    g_u1[(size_t)n * WIDTH + o] = __float2half_rn(sv);
                }
            }
        }
    }
}

// ---------------------------------------------------------------------------
// CONV2: compact N (grid.x=98), M=256 (grid.y=2), 9 taps x 4 k-chunks = 36.
// Boundary taps zero-filled via cp.async src-size=0.
// ---------------------------------------------------------------------------
__global__ void __launch_bounds__(256, 2) conv2_mma()
{
    extern __shared__ char smem[];
    const uint32_t sb = smem_u32(smem);
    const int tid = threadIdx.x, lane = tid & 31, wid = tid >> 5;
    const int wm = wid & 1, wn = wid >> 1;
    const int nbase = blockIdx.x * 128;
    const int mbase = blockIdx.y * 128;
    const int NCH = 36;

    float acc[4][4][4];
#pragma unroll
    for (int a = 0; a < 4; a++)
#pragma unroll
        for (int b = 0; b < 4; b++)
#pragma unroll
            for (int c = 0; c < 4; c++) acc[a][b][c] = 0.0f;

    auto prefetch = [&](int i) {
        const uint32_t base = sb + (i & 1) * BUFB;
        const int tap = i >> 2, kc = i & 3;
        const int dh = tap / 3 - 1, dw = tap % 3 - 1;
        const __half* wtap = g_w2h + (size_t)tap * WIDTH * WIDTH;
        for (int it = tid; it < 1024; it += 256) {
            int row = it >> 3, ch = it & 7;
            cpa16(base + row * PITCH + ch * 16,
                  &wtap[(size_t)(mbase + row) * WIDTH + kc * 64 + ch * 8]);
        }
        for (int it = tid; it < 1024; it += 256) {
            int row = it >> 3, ch = it & 7;
            int n = nbase + row;
            int b = n / HW, p = n - b * HW;
            int pr = p / 14, pc2 = p - pr * 14;
            bool valid = ((unsigned)(pr + dh) < 14u) && ((unsigned)(pc2 + dw) < 14u);
            int nsrc = valid ? (n + dh * 14 + dw) : 0;
            cpa16z(base + TILEB + row * PITCH + ch * 16,
                   &g_u1[(size_t)nsrc * WIDTH + kc * 64 + ch * 8], valid ? 16 : 0);
        }
        CP_COMMIT();
    };

    prefetch(0);
    for (int i = 0; i < NCH; i++) {
        if (i + 1 < NCH) { prefetch(i + 1); CP_WAIT1(); } else { CP_WAIT0(); }
        __syncthreads();
        const uint32_t base = sb + (i & 1) * BUFB;
        mma_chunk(base, base + TILEB, wm, wn, lane, acc);
        __syncthreads();
    }

#pragma unroll
    for (int mf = 0; mf < 4; mf++) {
#pragma unroll
        for (int half = 0; half < 2; half++) {
            const int o = mbase + wm * 64 + mf * 16 + (lane >> 2) + half * 8;
            const float sc = g_scale2[o], bi = g_bias2[o];
#pragma unroll
            for (int nf = 0; nf < 4; nf++) {
#pragma unroll
                for (int cc = 0; cc < 2; cc++) {
                    int n = nbase + wn * 32 + nf * 8 + (lane & 3) * 2 + cc;
                    float sv = silu_f(sc * acc[mf][nf][half * 2 + cc] + bi);
                    g_u2[(size_t)n * WIDTH + o] = __float2half_rn(sv);
                }
            }
        }
    }
}

// ---------------------------------------------------------------------------
// GEMM3 + residual + SiLU -> NCHW fp32. M=1024 (grid.y=8), N (grid.x=98), K=256.
// ---------------------------------------------------------------------------
__global__ void __launch_bounds__(256, 2) gemm3_mma(const float* __restrict__ x,
                                                    float* __restrict__ out)
{
    extern __shared__ char smem[];
    const uint32_t sb = smem_u32(smem);
    const int tid = threadIdx.x, lane = tid & 31, wid = tid >> 5;
    const int wm = wid & 1, wn = wid >> 1;
    const int nbase = blockIdx.x * 128;
    const int mbase = blockIdx.y * 128;
    const int NCH = 4;

    float acc[4][4][4];
#pragma unroll
    for (int a = 0; a < 4; a++)
#pragma unroll
        for (int b = 0; b < 4; b++)
#pragma unroll
            for (int c = 0; c < 4; c++) acc[a][b][c] = 0.0f;

    auto prefetch = [&](int i) {
        const uint32_t base = sb + (i & 1) * BUFB;
        const int kb = i * 64;
        for (int it = tid; it < 1024; it += 256) {
            int row = it >> 3, ch = it & 7;
            cpa16(base + row * PITCH + ch * 16,
                  &g_w3h[(size_t)(mbase + row) * WIDTH + kb + ch * 8]);
        }
        for (int it = tid; it < 1024; it += 256) {
            int row = it >> 3, ch = it & 7;
            cpa16(base + TILEB + row * PITCH + ch * 16,
                  &g_u2[(size_t)(nbase + row) * WIDTH + kb + ch * 8]);
        }
        CP_COMMIT();
    };

    prefetch(0);
    for (int i = 0; i < NCH; i++) {
        if (i + 1 < NCH) { prefetch(i + 1); CP_WAIT1(); } else { CP_WAIT0(); }
        __syncthreads();
        const uint32_t base = sb + (i & 1) * BUFB;
        mma_chunk(base, base + TILEB, wm, wn, lane, acc);
        __syncthreads();
    }

#pragma unroll
    for (int mf = 0; mf < 4; mf++) {
#pragma unroll
        for (int half = 0; half < 2; half++) {
            const int o = mbase + wm * 64 + mf * 16 + (lane >> 2) + half * 8;
            const float sc = g_scale3[o], bi = g_bias3[o];
#pragma unroll
            for (int nf = 0; nf < 4; nf++) {
#pragma unroll
                for (int cc = 0; cc < 2; cc++) {
                    int n = nbase + wn * 32 + nf * 8 + (lane & 3) * 2 + cc;
                    int b = n / HW, p = n - b * HW;
                    size_t idx = ((size_t)b * COUT + o) * HW + p;
                    float y = sc * acc[mf][nf][half * 2 + cc] + bi + x[idx];
                    out[idx] = silu_f(y);
                }
            }
        }
    }
}

// ---------------------------------------------------------------------------
extern "C" void kernel_launch(void* const* d_in, const int* in_sizes, int n_in,
                              void* d_out, int out_size)
{
    const float* x   = (const float*)d_in[0];
    const float* w1  = (const float*)d_in[1];
    const float* b1  = (const float*)d_in[2];
    const float* g1  = (const float*)d_in[3];
    const float* be1 = (const float*)d_in[4];
    const float* m1  = (const float*)d_in[5];
    const float* v1  = (const float*)d_in[6];
    const float* w2  = (const float*)d_in[7];
    const float* b2  = (const float*)d_in[8];
    const float* g2  = (const float*)d_in[9];
    const float* be2 = (const float*)d_in[10];
    const float* m2  = (const float*)d_in[11];
    const float* v2  = (const float*)d_in[12];
    const float* w3  = (const float*)d_in[13];
    const float* b3  = (const float*)d_in[14];
    const float* g3  = (const float*)d_in[15];
    const float* be3 = (const float*)d_in[16];
    const float* m3  = (const float*)d_in[17];
    const float* v3  = (const float*)d_in[18];
    float* out = (float*)d_out;

    cudaFuncSetAttribute(xconv_kernel, cudaFuncAttributeMaxDynamicSharedMemorySize, 50432);
    cudaFuncSetAttribute(gemm1_mma, cudaFuncAttributeMaxDynamicSharedMemorySize, SMEMB);
    cudaFuncSetAttribute(conv2_mma, cudaFuncAttributeMaxDynamicSharedMemorySize, SMEMB);
    cudaFuncSetAttribute(gemm3_mma, cudaFuncAttributeMaxDynamicSharedMemorySize, SMEMB);

    quant_all<<<1536, 256>>>(w1, b1, g1, be1, m1, v1,
                             w2, b2, g2, be2, m2, v2,
                             w3, b3, g3, be3, m3, v3);

    xconv_kernel<<<dim3(64, 16), 256, 50432>>>(x);

    gemm1_mma<<<dim3(98, 2), 256, SMEMB>>>();
    conv2_mma<<<dim3(98, 2), 256, SMEMB>>>();
    gemm3_mma<<<dim3(98, 8), 256, SMEMB>>>(x, out);
}